// round 2
// baseline (speedup 1.0000x reference)
#include <cuda_runtime.h>
#include <math.h>

#define S_IMG 2048
#define S_TXT 512
#define S_TOT 2560
#define DM    3072
#define NH    24
#define HD    128
#define ATOK  4
#define ADIM  1024
#define SM_SCALE 0.08838834764831845f  /* 1/sqrt(128) */

// ---------------- scratch (device globals; no allocation allowed) ----------------
__device__ float g_pq_img[(size_t)S_IMG * DM];
__device__ float g_pk_img[(size_t)S_IMG * DM];
__device__ float g_pv_img[(size_t)S_IMG * DM];
__device__ float g_pq_txt[(size_t)S_TXT * DM];
__device__ float g_pk_txt[(size_t)S_TXT * DM];
__device__ float g_pv_txt[(size_t)S_TXT * DM];
__device__ float g_q[(size_t)NH * S_TOT * HD];
__device__ float g_k[(size_t)NH * S_TOT * HD];
__device__ float g_v[(size_t)NH * S_TOT * HD];
__device__ float g_o[(size_t)NH * S_TOT * HD];
__device__ float g_hs[(size_t)S_TOT * DM];
__device__ float g_ka[ATOK * DM];
__device__ float g_va[ATOK * DM];

// ---------------- generic SGEMM: C[M,N=3072] = A[M,K] @ W[K,3072] + bias -----------
__global__ __launch_bounds__(256) void sgemm_bias(
    const float* __restrict__ A, const float* __restrict__ W,
    const float* __restrict__ bias, float* __restrict__ C,
    int M, int K)
{
    __shared__ float As[16][128];   // transposed A tile: As[k][m]
    __shared__ float Bs[16][128];
    const int n0 = blockIdx.x * 128;
    const int m0 = blockIdx.y * 128;
    const int tid = threadIdx.x;
    const int ar = tid >> 2, ac = tid & 3;    // A loader: row, k-float4
    const int br = tid >> 5, bc = tid & 31;   // B loader: k-row, n-float4
    const int tr = tid >> 4, tc = tid & 15;   // compute: 16x16 threads, 8x8 each

    float acc[8][8];
    #pragma unroll
    for (int i = 0; i < 8; i++)
        #pragma unroll
        for (int j = 0; j < 8; j++) acc[i][j] = 0.f;

    for (int k0 = 0; k0 < K; k0 += 16) {
        #pragma unroll
        for (int t = 0; t < 2; t++) {
            int m = m0 + ar + t * 64;
            float4 av = make_float4(0.f, 0.f, 0.f, 0.f);
            if (m < M) av = *(const float4*)&A[(size_t)m * K + k0 + ac * 4];
            As[ac * 4 + 0][ar + t * 64] = av.x;
            As[ac * 4 + 1][ar + t * 64] = av.y;
            As[ac * 4 + 2][ar + t * 64] = av.z;
            As[ac * 4 + 3][ar + t * 64] = av.w;
        }
        #pragma unroll
        for (int t = 0; t < 2; t++) {
            int kk = br + t * 8;
            *(float4*)&Bs[kk][bc * 4] =
                *(const float4*)&W[(size_t)(k0 + kk) * DM + n0 + bc * 4];
        }
        __syncthreads();
        #pragma unroll
        for (int kk = 0; kk < 16; kk++) {
            float a[8], b[8];
            *(float4*)&a[0] = *(const float4*)&As[kk][tr * 8];
            *(float4*)&a[4] = *(const float4*)&As[kk][tr * 8 + 4];
            *(float4*)&b[0] = *(const float4*)&Bs[kk][tc * 8];
            *(float4*)&b[4] = *(const float4*)&Bs[kk][tc * 8 + 4];
            #pragma unroll
            for (int i = 0; i < 8; i++)
                #pragma unroll
                for (int j = 0; j < 8; j++)
                    acc[i][j] += a[i] * b[j];
        }
        __syncthreads();
    }
    float bv[8];
    #pragma unroll
    for (int j = 0; j < 8; j++) bv[j] = bias ? bias[n0 + tc * 8 + j] : 0.f;
    #pragma unroll
    for (int i = 0; i < 8; i++) {
        int m = m0 + tr * 8 + i;
        if (m < M) {
            float* crow = C + (size_t)m * DM + n0 + tc * 8;
            *(float4*)crow = make_float4(acc[i][0] + bv[0], acc[i][1] + bv[1],
                                         acc[i][2] + bv[2], acc[i][3] + bv[3]);
            *(float4*)(crow + 4) = make_float4(acc[i][4] + bv[4], acc[i][5] + bv[5],
                                               acc[i][6] + bv[6], acc[i][7] + bv[7]);
        }
    }
}

// ------------- RMSNorm + RoPE + concat into [H, S_TOT, HD] --------------------
__global__ __launch_bounds__(128) void qkv_transform(
    const float* __restrict__ nqw, const float* __restrict__ nkw,
    const float* __restrict__ naqw, const float* __restrict__ nakw,
    const float* __restrict__ fcos, const float* __restrict__ fsin)
{
    const int s = blockIdx.x, h = blockIdx.y, d = threadIdx.x;
    const int lane = d & 31, wid = d >> 5;
    __shared__ float ws[4];
    const bool txt = s < S_TXT;
    const size_t roff = txt ? (size_t)s * DM : (size_t)(s - S_TXT) * DM;
    const size_t col = roff + h * HD + d;
    const float* xq = txt ? g_pq_txt : g_pq_img;
    const float* xk = txt ? g_pk_txt : g_pk_img;
    const float* xv = txt ? g_pv_txt : g_pv_img;
    const float wq = txt ? naqw[d] : nqw[d];
    const float wk = txt ? nakw[d] : nkw[d];
    const float c = fcos[s * HD + d];
    const float sn = fsin[s * HD + d];
    const size_t oidx = ((size_t)h * S_TOT + s) * HD + d;

    // ---- q: rms + rope ----
    float q = xq[col];
    float t2 = q * q;
    #pragma unroll
    for (int off = 16; off; off >>= 1) t2 += __shfl_xor_sync(0xffffffffu, t2, off);
    if (lane == 0) ws[wid] = t2;
    __syncthreads();
    float tot = ws[0] + ws[1] + ws[2] + ws[3];
    float qn = q * rsqrtf(tot * (1.f / HD) + 1e-6f) * wq;
    float pq = __shfl_xor_sync(0xffffffffu, qn, 1);
    float rotq = (d & 1) ? pq : -pq;
    g_q[oidx] = qn * c + rotq * sn;
    __syncthreads();

    // ---- k: rms + rope ----
    float k = xk[col];
    t2 = k * k;
    #pragma unroll
    for (int off = 16; off; off >>= 1) t2 += __shfl_xor_sync(0xffffffffu, t2, off);
    if (lane == 0) ws[wid] = t2;
    __syncthreads();
    tot = ws[0] + ws[1] + ws[2] + ws[3];
    float kn = k * rsqrtf(tot * (1.f / HD) + 1e-6f) * wk;
    float pk = __shfl_xor_sync(0xffffffffu, kn, 1);
    float rotk = (d & 1) ? pk : -pk;
    g_k[oidx] = kn * c + rotk * sn;

    // ---- v: copy ----
    g_v[oidx] = xv[col];
}

// ---------------- flash attention, fp32, BQ=64, BK=32 -------------------------
// 128 threads: thread = (row = tid>>1, half = tid&1 owning 64 dims)
#define ROWPAD 132
__global__ __launch_bounds__(128) void attn_fa()
{
    extern __shared__ float smf[];
    float* Qs = smf;                    // 64 x 132
    float* Ks = smf + 64 * ROWPAD;      // 32 x 132
    float* Vs = smf + 96 * ROWPAD;      // 32 x 132
    const int qt = blockIdx.x, h = blockIdx.y;
    const int tid = threadIdx.x;
    const float* Qg = g_q + ((size_t)h * S_TOT + qt * 64) * HD;
    const float* Kg0 = g_k + (size_t)h * S_TOT * HD;
    const float* Vg0 = g_v + (size_t)h * S_TOT * HD;

    for (int i = tid; i < 64 * 32; i += 128) {
        int r = i >> 5, c4 = i & 31;
        *(float4*)&Qs[r * ROWPAD + c4 * 4] = *(const float4*)&Qg[r * HD + c4 * 4];
    }
    const int row = tid >> 1, hf = tid & 1, dbase = hf * 64;
    const float* qrow = &Qs[row * ROWPAD + dbase];
    float m = -1e30f, l = 0.f;
    float acc[64];
    #pragma unroll
    for (int i = 0; i < 64; i++) acc[i] = 0.f;

    for (int kt = 0; kt < S_TOT / 32; kt++) {
        __syncthreads();
        const float* Kg = Kg0 + (size_t)kt * 32 * HD;
        const float* Vg = Vg0 + (size_t)kt * 32 * HD;
        for (int i = tid; i < 32 * 32; i += 128) {
            int r = i >> 5, c4 = i & 31;
            *(float4*)&Ks[r * ROWPAD + c4 * 4] = *(const float4*)&Kg[r * HD + c4 * 4];
            *(float4*)&Vs[r * ROWPAD + c4 * 4] = *(const float4*)&Vg[r * HD + c4 * 4];
        }
        __syncthreads();

        float s[32];
        #pragma unroll
        for (int j = 0; j < 32; j++) s[j] = 0.f;
        for (int db = 0; db < 64; db += 8) {
            float q0 = qrow[db + 0], q1 = qrow[db + 1], q2 = qrow[db + 2], q3 = qrow[db + 3];
            float q4 = qrow[db + 4], q5 = qrow[db + 5], q6 = qrow[db + 6], q7 = qrow[db + 7];
            #pragma unroll
            for (int j = 0; j < 32; j++) {
                const float* kr = &Ks[j * ROWPAD + dbase + db];
                float4 k0 = *(const float4*)kr;
                float4 k1 = *(const float4*)(kr + 4);
                s[j] += q0 * k0.x + q1 * k0.y + q2 * k0.z + q3 * k0.w
                      + q4 * k1.x + q5 * k1.y + q6 * k1.z + q7 * k1.w;
            }
        }
        float mt = m;
        #pragma unroll
        for (int j = 0; j < 32; j++) {
            s[j] = (s[j] + __shfl_xor_sync(0xffffffffu, s[j], 1)) * SM_SCALE;
            mt = fmaxf(mt, s[j]);
        }
        float corr = __expf(m - mt);
        float lsum = 0.f;
        #pragma unroll
        for (int j = 0; j < 32; j++) { float p = __expf(s[j] - mt); s[j] = p; lsum += p; }
        m = mt;
        l = l * corr + lsum;
        #pragma unroll
        for (int i = 0; i < 64; i++) acc[i] *= corr;
        #pragma unroll
        for (int j = 0; j < 32; j++) {
            float p = s[j];
            const float* vr = &Vs[j * ROWPAD + dbase];
            #pragma unroll
            for (int q4 = 0; q4 < 16; q4++) {
                float4 vv = *(const float4*)&vr[q4 * 4];
                acc[q4 * 4 + 0] += p * vv.x;
                acc[q4 * 4 + 1] += p * vv.y;
                acc[q4 * 4 + 2] += p * vv.z;
                acc[q4 * 4 + 3] += p * vv.w;
            }
        }
    }
    float inv = 1.f / l;
    float* Or = g_o + ((size_t)h * S_TOT + qt * 64 + row) * HD + dbase;
    #pragma unroll
    for (int i = 0; i < 64; i += 4) {
        *(float4*)&Or[i] = make_float4(acc[i] * inv, acc[i + 1] * inv,
                                       acc[i + 2] * inv, acc[i + 3] * inv);
    }
}

// ------- adapter 4-key cross-attention + merge into [S_TOT, DM] ----------------
__global__ __launch_bounds__(128) void merge_adapter(const float* __restrict__ bscale)
{
    const int s = blockIdx.x, h = blockIdx.y, d = threadIdx.x;
    const int lane = d & 31, wid = d >> 5;
    __shared__ float wsum[4];
    __shared__ float sd[4];
    const size_t qidx = ((size_t)h * S_TOT + s) * HD + d;
    const float qv = g_q[qidx];
    const int hcol = h * HD + d;
    #pragma unroll
    for (int t = 0; t < ATOK; t++) {
        float p = qv * g_ka[t * DM + hcol];
        #pragma unroll
        for (int off = 16; off; off >>= 1) p += __shfl_xor_sync(0xffffffffu, p, off);
        if (lane == 0) wsum[wid] = p;
        __syncthreads();
        if (d == 0) sd[t] = (wsum[0] + wsum[1] + wsum[2] + wsum[3]) * SM_SCALE;
        __syncthreads();
    }
    float d0 = sd[0], d1 = sd[1], d2 = sd[2], d3 = sd[3];
    float mx = fmaxf(fmaxf(d0, d1), fmaxf(d2, d3));
    float e0 = __expf(d0 - mx), e1 = __expf(d1 - mx);
    float e2 = __expf(d2 - mx), e3 = __expf(d3 - mx);
    float inv = 1.f / (e0 + e1 + e2 + e3);
    float vd = (e0 * g_va[0 * DM + hcol] + e1 * g_va[1 * DM + hcol] +
                e2 * g_va[2 * DM + hcol] + e3 * g_va[3 * DM + hcol]) * inv;
    g_hs[(size_t)s * DM + hcol] = g_o[qidx] + bscale[0] * vd;
}

// -------------------------------- launch ---------------------------------------
extern "C" void kernel_launch(void* const* d_in, const int* in_sizes, int n_in,
                              void* d_out, int out_size)
{
    const float* hidden = (const float*)d_in[0];
    const float* enc    = (const float*)d_in[1];
    const float* adapt  = (const float*)d_in[2];
    const float* fcos   = (const float*)d_in[3];
    const float* fsin   = (const float*)d_in[4];
    const float* Wq  = (const float*)d_in[5];  const float* bq  = (const float*)d_in[6];
    const float* Wk  = (const float*)d_in[7];  const float* bk  = (const float*)d_in[8];
    const float* Wv  = (const float*)d_in[9];  const float* bv  = (const float*)d_in[10];
    const float* nqw = (const float*)d_in[11]; const float* nkw = (const float*)d_in[12];
    const float* Wqa = (const float*)d_in[13]; const float* bqa = (const float*)d_in[14];
    const float* Wka = (const float*)d_in[15]; const float* bka = (const float*)d_in[16];
    const float* Wva = (const float*)d_in[17]; const float* bva = (const float*)d_in[18];
    const float* naqw = (const float*)d_in[19]; const float* nakw = (const float*)d_in[20];
    const float* Wo  = (const float*)d_in[21]; const float* bo  = (const float*)d_in[22];
    const float* Woa = (const float*)d_in[23]; const float* boa = (const float*)d_in[24];
    const float* Wkad = (const float*)d_in[25]; const float* Wvad = (const float*)d_in[26];
    const float* bscale = (const float*)d_in[27];
    float* out = (float*)d_out;

    float *pq_img, *pk_img, *pv_img, *pq_txt, *pk_txt, *pv_txt, *ka, *va, *hs;
    cudaGetSymbolAddress((void**)&pq_img, g_pq_img);
    cudaGetSymbolAddress((void**)&pk_img, g_pk_img);
    cudaGetSymbolAddress((void**)&pv_img, g_pv_img);
    cudaGetSymbolAddress((void**)&pq_txt, g_pq_txt);
    cudaGetSymbolAddress((void**)&pk_txt, g_pk_txt);
    cudaGetSymbolAddress((void**)&pv_txt, g_pv_txt);
    cudaGetSymbolAddress((void**)&ka, g_ka);
    cudaGetSymbolAddress((void**)&va, g_va);
    cudaGetSymbolAddress((void**)&hs, g_hs);

    cudaFuncSetAttribute(attn_fa, cudaFuncAttributeMaxDynamicSharedMemorySize,
                         128 * ROWPAD * 4);

    // QKV projections
    sgemm_bias<<<dim3(DM / 128, S_IMG / 128), 256>>>(hidden, Wq, bq, pq_img, S_IMG, DM);
    sgemm_bias<<<dim3(DM / 128, S_IMG / 128), 256>>>(hidden, Wk, bk, pk_img, S_IMG, DM);
    sgemm_bias<<<dim3(DM / 128, S_IMG / 128), 256>>>(hidden, Wv, bv, pv_img, S_IMG, DM);
    sgemm_bias<<<dim3(DM / 128, S_TXT / 128), 256>>>(enc, Wqa, bqa, pq_txt, S_TXT, DM);
    sgemm_bias<<<dim3(DM / 128, S_TXT / 128), 256>>>(enc, Wka, bka, pk_txt, S_TXT, DM);
    sgemm_bias<<<dim3(DM / 128, S_TXT / 128), 256>>>(enc, Wva, bva, pv_txt, S_TXT, DM);
    // adapter K/V (M=4, K=1024, no bias)
    sgemm_bias<<<dim3(DM / 128, 1), 256>>>(adapt, Wkad, (const float*)0, ka, ATOK, ADIM);
    sgemm_bias<<<dim3(DM / 128, 1), 256>>>(adapt, Wvad, (const float*)0, va, ATOK, ADIM);

    // RMSNorm + RoPE + head layout
    qkv_transform<<<dim3(S_TOT, NH), 128>>>(nqw, nkw, naqw, nakw, fcos, fsin);
    // joint flash attention
    attn_fa<<<dim3(S_TOT / 64, NH), 128, 128 * ROWPAD * 4>>>();
    // adapter attention + merge
    merge_adapter<<<dim3(S_TOT, NH), 128>>>(bscale);

    // output projections: d_out = [img_out (2048x3072), enc_out (512x3072)]
    sgemm_bias<<<dim3(DM / 128, S_IMG / 128), 256>>>(hs + (size_t)S_TXT * DM, Wo, bo,
                                                     out, S_IMG, DM);
    sgemm_bias<<<dim3(DM / 128, (S_TXT + 127) / 128), 256>>>(hs, Woa, boa,
                                                             out + (size_t)S_IMG * DM,
                                                             S_TXT, DM);
}

// round 5
// speedup vs baseline: 1.1936x; 1.1936x over previous
#include <cuda_runtime.h>
#include <math.h>
#include <stdint.h>

#define S_IMG 2048
#define S_TXT 512
#define S_TOT 2560
#define DM    3072
#define NH    24
#define HD    128
#define ATOK  4
#define ADIM  1024
#define SM_SCALE 0.08838834764831845f  /* 1/sqrt(128) */

// ---------------- scratch (device globals; no allocation allowed) ----------------
__device__ float g_pq_img[(size_t)S_IMG * DM];
__device__ float g_pk_img[(size_t)S_IMG * DM];
__device__ float g_pv_img[(size_t)S_IMG * DM];
__device__ float g_pq_txt[(size_t)S_TXT * DM];
__device__ float g_pk_txt[(size_t)S_TXT * DM];
__device__ float g_pv_txt[(size_t)S_TXT * DM];
__device__ float g_q[(size_t)NH * S_TOT * HD];
__device__ float g_k[(size_t)NH * S_TOT * HD];
__device__ float g_v[(size_t)NH * S_TOT * HD];
__device__ float g_o[(size_t)NH * S_TOT * HD];
__device__ float g_hs[(size_t)S_TOT * DM];
__device__ float g_ka[ATOK * DM];
__device__ float g_va[ATOK * DM];

// ------------------------- tf32 helpers ----------------------------------------
__device__ __forceinline__ uint32_t f2tf32(float f) {
    uint32_t r;
    asm("cvt.rna.tf32.f32 %0, %1;" : "=r"(r) : "f"(f));
    return r;
}

__device__ __forceinline__ void mma_tf32(float4& d, const uint32_t a[4],
                                         const uint32_t b[2]) {
    asm volatile(
        "mma.sync.aligned.m16n8k8.row.col.f32.tf32.tf32.f32 "
        "{%0,%1,%2,%3}, {%4,%5,%6,%7}, {%8,%9}, {%0,%1,%2,%3};\n"
        : "+f"(d.x), "+f"(d.y), "+f"(d.z), "+f"(d.w)
        : "r"(a[0]), "r"(a[1]), "r"(a[2]), "r"(a[3]), "r"(b[0]), "r"(b[1]));
}

// ---------- tf32 tensor-core GEMM: C[M,3072] = A[M,K] @ W[K,3072] + bias ----------
// CTA tile 128x128, BK=32, 8 warps each computing a 32x64 warp tile.
#define BM 128
#define BN 128
#define BK 32
#define PADA 36    /* As[BM][PADA]: frag-read bank = 4*tig + gid (bijective) */
#define PADB 136   /* Bs[BK][PADB]: frag-read bank = 8*tig + gid (bijective) */

__global__ __launch_bounds__(256) void gemm_tf32(
    const float* __restrict__ A, const float* __restrict__ W,
    const float* __restrict__ bias, float* __restrict__ C,
    int M, int K)
{
    __shared__ float As[BM][PADA];
    __shared__ float Bs[BK][PADB];
    const int tid  = threadIdx.x;
    const int warp = tid >> 5, lane = tid & 31;
    const int gid  = lane >> 2, tig = lane & 3;
    const int wm = (warp & 3) * 32;    // warp row offset in tile
    const int wn = (warp >> 2) * 64;   // warp col offset in tile
    const int m0 = blockIdx.y * BM;
    const int n0 = blockIdx.x * BN;

    float4 acc[2][8];
    #pragma unroll
    for (int i = 0; i < 2; i++)
        #pragma unroll
        for (int j = 0; j < 8; j++) acc[i][j] = make_float4(0.f, 0.f, 0.f, 0.f);

    const int arow = tid >> 3, acol = (tid & 7) * 4;   // A loader
    const int brow = tid >> 5, bcol = (tid & 31) * 4;  // B loader

    for (int k0 = 0; k0 < K; k0 += BK) {
        // stage A tile (rows 128 x k 32), convert to tf32 bits
        #pragma unroll
        for (int p = 0; p < 4; p++) {
            int m = m0 + arow + p * 32;
            float4 v = make_float4(0.f, 0.f, 0.f, 0.f);
            if (m < M) v = *(const float4*)&A[(size_t)m * K + k0 + acol];
            float4 t;
            t.x = __uint_as_float(f2tf32(v.x));
            t.y = __uint_as_float(f2tf32(v.y));
            t.z = __uint_as_float(f2tf32(v.z));
            t.w = __uint_as_float(f2tf32(v.w));
            *(float4*)&As[arow + p * 32][acol] = t;
        }
        // stage B tile (k 32 x n 128)
        #pragma unroll
        for (int p = 0; p < 4; p++) {
            int kk = brow + p * 8;
            float4 v = *(const float4*)&W[(size_t)(k0 + kk) * DM + n0 + bcol];
            float4 t;
            t.x = __uint_as_float(f2tf32(v.x));
            t.y = __uint_as_float(f2tf32(v.y));
            t.z = __uint_as_float(f2tf32(v.z));
            t.w = __uint_as_float(f2tf32(v.w));
            *(float4*)&Bs[kk][bcol] = t;
        }
        __syncthreads();

        #pragma unroll
        for (int kk = 0; kk < BK; kk += 8) {
            uint32_t af[2][4];
            #pragma unroll
            for (int mt = 0; mt < 2; mt++) {
                int r = wm + mt * 16 + gid;
                af[mt][0] = __float_as_uint(As[r][kk + tig]);
                af[mt][1] = __float_as_uint(As[r + 8][kk + tig]);
                af[mt][2] = __float_as_uint(As[r][kk + tig + 4]);
                af[mt][3] = __float_as_uint(As[r + 8][kk + tig + 4]);
            }
            uint32_t bf[8][2];
            #pragma unroll
            for (int nt = 0; nt < 8; nt++) {
                int c = wn + nt * 8 + gid;
                bf[nt][0] = __float_as_uint(Bs[kk + tig][c]);
                bf[nt][1] = __float_as_uint(Bs[kk + tig + 4][c]);
            }
            #pragma unroll
            for (int mt = 0; mt < 2; mt++)
                #pragma unroll
                for (int nt = 0; nt < 8; nt++)
                    mma_tf32(acc[mt][nt], af[mt], bf[nt]);
        }
        __syncthreads();
    }

    // epilogue: c0,c1 -> row gid cols 2*tig,2*tig+1 ; c2,c3 -> row gid+8
    #pragma unroll
    for (int mt = 0; mt < 2; mt++) {
        int r0 = m0 + wm + mt * 16 + gid;
        #pragma unroll
        for (int nt = 0; nt < 8; nt++) {
            int col = n0 + wn + nt * 8 + tig * 2;
            float b0 = bias ? bias[col] : 0.f;
            float b1 = bias ? bias[col + 1] : 0.f;
            if (r0 < M) {
                float2* p = (float2*)&C[(size_t)r0 * DM + col];
                *p = make_float2(acc[mt][nt].x + b0, acc[mt][nt].y + b1);
            }
            if (r0 + 8 < M) {
                float2* p = (float2*)&C[(size_t)(r0 + 8) * DM + col];
                *p = make_float2(acc[mt][nt].z + b0, acc[mt][nt].w + b1);
            }
        }
    }
}

// ------------- RMSNorm + RoPE + concat into [H, S_TOT, HD] --------------------
__global__ __launch_bounds__(128) void qkv_transform(
    const float* __restrict__ nqw, const float* __restrict__ nkw,
    const float* __restrict__ naqw, const float* __restrict__ nakw,
    const float* __restrict__ fcos, const float* __restrict__ fsin)
{
    const int s = blockIdx.x, h = blockIdx.y, d = threadIdx.x;
    const int lane = d & 31, wid = d >> 5;
    __shared__ float ws[4];
    const bool txt = s < S_TXT;
    const size_t roff = txt ? (size_t)s * DM : (size_t)(s - S_TXT) * DM;
    const size_t col = roff + h * HD + d;
    const float* xq = txt ? g_pq_txt : g_pq_img;
    const float* xk = txt ? g_pk_txt : g_pk_img;
    const float* xv = txt ? g_pv_txt : g_pv_img;
    const float wq = txt ? naqw[d] : nqw[d];
    const float wk = txt ? nakw[d] : nkw[d];
    const float c = fcos[s * HD + d];
    const float sn = fsin[s * HD + d];
    const size_t oidx = ((size_t)h * S_TOT + s) * HD + d;

    // ---- q: rms + rope ----
    float q = xq[col];
    float t2 = q * q;
    #pragma unroll
    for (int off = 16; off; off >>= 1) t2 += __shfl_xor_sync(0xffffffffu, t2, off);
    if (lane == 0) ws[wid] = t2;
    __syncthreads();
    float tot = ws[0] + ws[1] + ws[2] + ws[3];
    float qn = q * rsqrtf(tot * (1.f / HD) + 1e-6f) * wq;
    float pq = __shfl_xor_sync(0xffffffffu, qn, 1);
    float rotq = (d & 1) ? pq : -pq;
    g_q[oidx] = qn * c + rotq * sn;
    __syncthreads();

    // ---- k: rms + rope ----
    float k = xk[col];
    t2 = k * k;
    #pragma unroll
    for (int off = 16; off; off >>= 1) t2 += __shfl_xor_sync(0xffffffffu, t2, off);
    if (lane == 0) ws[wid] = t2;
    __syncthreads();
    tot = ws[0] + ws[1] + ws[2] + ws[3];
    float kn = k * rsqrtf(tot * (1.f / HD) + 1e-6f) * wk;
    float pk = __shfl_xor_sync(0xffffffffu, kn, 1);
    float rotk = (d & 1) ? pk : -pk;
    g_k[oidx] = kn * c + rotk * sn;

    // ---- v: copy ----
    g_v[oidx] = xv[col];
}

// ---------------- flash attention, fp32, BQ=64, BK=32 -------------------------
// 128 threads: thread = (row = tid>>1, half = tid&1 owning 64 dims)
#define ROWPAD 132
__global__ __launch_bounds__(128) void attn_fa()
{
    extern __shared__ float smf[];
    float* Qs = smf;                    // 64 x 132
    float* Ks = smf + 64 * ROWPAD;      // 32 x 132
    float* Vs = smf + 96 * ROWPAD;      // 32 x 132
    const int qt = blockIdx.x, h = blockIdx.y;
    const int tid = threadIdx.x;
    const float* Qg = g_q + ((size_t)h * S_TOT + qt * 64) * HD;
    const float* Kg0 = g_k + (size_t)h * S_TOT * HD;
    const float* Vg0 = g_v + (size_t)h * S_TOT * HD;

    for (int i = tid; i < 64 * 32; i += 128) {
        int r = i >> 5, c4 = i & 31;
        *(float4*)&Qs[r * ROWPAD + c4 * 4] = *(const float4*)&Qg[r * HD + c4 * 4];
    }
    const int row = tid >> 1, hf = tid & 1, dbase = hf * 64;
    const float* qrow = &Qs[row * ROWPAD + dbase];
    float m = -1e30f, l = 0.f;
    float acc[64];
    #pragma unroll
    for (int i = 0; i < 64; i++) acc[i] = 0.f;

    for (int kt = 0; kt < S_TOT / 32; kt++) {
        __syncthreads();
        const float* Kg = Kg0 + (size_t)kt * 32 * HD;
        const float* Vg = Vg0 + (size_t)kt * 32 * HD;
        for (int i = tid; i < 32 * 32; i += 128) {
            int r = i >> 5, c4 = i & 31;
            *(float4*)&Ks[r * ROWPAD + c4 * 4] = *(const float4*)&Kg[r * HD + c4 * 4];
            *(float4*)&Vs[r * ROWPAD + c4 * 4] = *(const float4*)&Vg[r * HD + c4 * 4];
        }
        __syncthreads();

        float s[32];
        #pragma unroll
        for (int j = 0; j < 32; j++) s[j] = 0.f;
        for (int db = 0; db < 64; db += 8) {
            float q0 = qrow[db + 0], q1 = qrow[db + 1], q2 = qrow[db + 2], q3 = qrow[db + 3];
            float q4 = qrow[db + 4], q5 = qrow[db + 5], q6 = qrow[db + 6], q7 = qrow[db + 7];
            #pragma unroll
            for (int j = 0; j < 32; j++) {
                const float* kr = &Ks[j * ROWPAD + dbase + db];
                float4 k0 = *(const float4*)kr;
                float4 k1 = *(const float4*)(kr + 4);
                s[j] += q0 * k0.x + q1 * k0.y + q2 * k0.z + q3 * k0.w
                      + q4 * k1.x + q5 * k1.y + q6 * k1.z + q7 * k1.w;
            }
        }
        float mt = m;
        #pragma unroll
        for (int j = 0; j < 32; j++) {
            s[j] = (s[j] + __shfl_xor_sync(0xffffffffu, s[j], 1)) * SM_SCALE;
            mt = fmaxf(mt, s[j]);
        }
        float corr = __expf(m - mt);
        float lsum = 0.f;
        #pragma unroll
        for (int j = 0; j < 32; j++) { float p = __expf(s[j] - mt); s[j] = p; lsum += p; }
        m = mt;
        l = l * corr + lsum;
        #pragma unroll
        for (int i = 0; i < 64; i++) acc[i] *= corr;
        #pragma unroll
        for (int j = 0; j < 32; j++) {
            float p = s[j];
            const float* vr = &Vs[j * ROWPAD + dbase];
            #pragma unroll
            for (int q4 = 0; q4 < 16; q4++) {
                float4 vv = *(const float4*)&vr[q4 * 4];
                acc[q4 * 4 + 0] += p * vv.x;
                acc[q4 * 4 + 1] += p * vv.y;
                acc[q4 * 4 + 2] += p * vv.z;
                acc[q4 * 4 + 3] += p * vv.w;
            }
        }
    }
    float inv = 1.f / l;
    float* Or = g_o + ((size_t)h * S_TOT + qt * 64 + row) * HD + dbase;
    #pragma unroll
    for (int i = 0; i < 64; i += 4) {
        *(float4*)&Or[i] = make_float4(acc[i] * inv, acc[i + 1] * inv,
                                       acc[i + 2] * inv, acc[i + 3] * inv);
    }
}

// ------- adapter 4-key cross-attention + merge into [S_TOT, DM] ----------------
__global__ __launch_bounds__(128) void merge_adapter(const float* __restrict__ bscale)
{
    const int s = blockIdx.x, h = blockIdx.y, d = threadIdx.x;
    const int lane = d & 31, wid = d >> 5;
    __shared__ float wsum[4];
    __shared__ float sd[4];
    const size_t qidx = ((size_t)h * S_TOT + s) * HD + d;
    const float qv = g_q[qidx];
    const int hcol = h * HD + d;
    #pragma unroll
    for (int t = 0; t < ATOK; t++) {
        float p = qv * g_ka[t * DM + hcol];
        #pragma unroll
        for (int off = 16; off; off >>= 1) p += __shfl_xor_sync(0xffffffffu, p, off);
        if (lane == 0) wsum[wid] = p;
        __syncthreads();
        if (d == 0) sd[t] = (wsum[0] + wsum[1] + wsum[2] + wsum[3]) * SM_SCALE;
        __syncthreads();
    }
    float d0 = sd[0], d1 = sd[1], d2 = sd[2], d3 = sd[3];
    float mx = fmaxf(fmaxf(d0, d1), fmaxf(d2, d3));
    float e0 = __expf(d0 - mx), e1 = __expf(d1 - mx);
    float e2 = __expf(d2 - mx), e3 = __expf(d3 - mx);
    float inv = 1.f / (e0 + e1 + e2 + e3);
    float vd = (e0 * g_va[0 * DM + hcol] + e1 * g_va[1 * DM + hcol] +
                e2 * g_va[2 * DM + hcol] + e3 * g_va[3 * DM + hcol]) * inv;
    g_hs[(size_t)s * DM + hcol] = g_o[qidx] + bscale[0] * vd;
}

// -------------------------------- launch ---------------------------------------
extern "C" void kernel_launch(void* const* d_in, const int* in_sizes, int n_in,
                              void* d_out, int out_size)
{
    const float* hidden = (const float*)d_in[0];
    const float* enc    = (const float*)d_in[1];
    const float* adapt  = (const float*)d_in[2];
    const float* fcos   = (const float*)d_in[3];
    const float* fsin   = (const float*)d_in[4];
    const float* Wq  = (const float*)d_in[5];  const float* bq  = (const float*)d_in[6];
    const float* Wk  = (const float*)d_in[7];  const float* bk  = (const float*)d_in[8];
    const float* Wv  = (const float*)d_in[9];  const float* bv  = (const float*)d_in[10];
    const float* nqw = (const float*)d_in[11]; const float* nkw = (const float*)d_in[12];
    const float* Wqa = (const float*)d_in[13]; const float* bqa = (const float*)d_in[14];
    const float* Wka = (const float*)d_in[15]; const float* bka = (const float*)d_in[16];
    const float* Wva = (const float*)d_in[17]; const float* bva = (const float*)d_in[18];
    const float* naqw = (const float*)d_in[19]; const float* nakw = (const float*)d_in[20];
    const float* Wo  = (const float*)d_in[21]; const float* bo  = (const float*)d_in[22];
    const float* Woa = (const float*)d_in[23]; const float* boa = (const float*)d_in[24];
    const float* Wkad = (const float*)d_in[25]; const float* Wvad = (const float*)d_in[26];
    const float* bscale = (const float*)d_in[27];
    float* out = (float*)d_out;

    float *pq_img, *pk_img, *pv_img, *pq_txt, *pk_txt, *pv_txt, *ka, *va, *hs;
    cudaGetSymbolAddress((void**)&pq_img, g_pq_img);
    cudaGetSymbolAddress((void**)&pk_img, g_pk_img);
    cudaGetSymbolAddress((void**)&pv_img, g_pv_img);
    cudaGetSymbolAddress((void**)&pq_txt, g_pq_txt);
    cudaGetSymbolAddress((void**)&pk_txt, g_pk_txt);
    cudaGetSymbolAddress((void**)&pv_txt, g_pv_txt);
    cudaGetSymbolAddress((void**)&ka, g_ka);
    cudaGetSymbolAddress((void**)&va, g_va);
    cudaGetSymbolAddress((void**)&hs, g_hs);

    cudaFuncSetAttribute(attn_fa, cudaFuncAttributeMaxDynamicSharedMemorySize,
                         128 * ROWPAD * 4);

    // QKV projections (tf32 tensor cores)
    gemm_tf32<<<dim3(DM / BN, S_IMG / BM), 256>>>(hidden, Wq, bq, pq_img, S_IMG, DM);
    gemm_tf32<<<dim3(DM / BN, S_IMG / BM), 256>>>(hidden, Wk, bk, pk_img, S_IMG, DM);
    gemm_tf32<<<dim3(DM / BN, S_IMG / BM), 256>>>(hidden, Wv, bv, pv_img, S_IMG, DM);
    gemm_tf32<<<dim3(DM / BN, S_TXT / BM), 256>>>(enc, Wqa, bqa, pq_txt, S_TXT, DM);
    gemm_tf32<<<dim3(DM / BN, S_TXT / BM), 256>>>(enc, Wka, bka, pk_txt, S_TXT, DM);
    gemm_tf32<<<dim3(DM / BN, S_TXT / BM), 256>>>(enc, Wva, bva, pv_txt, S_TXT, DM);
    // adapter K/V (M=4, K=1024, no bias)
    gemm_tf32<<<dim3(DM / BN, 1), 256>>>(adapt, Wkad, (const float*)0, ka, ATOK, ADIM);
    gemm_tf32<<<dim3(DM / BN, 1), 256>>>(adapt, Wvad, (const float*)0, va, ATOK, ADIM);

    // RMSNorm + RoPE + head layout
    qkv_transform<<<dim3(S_TOT, NH), 128>>>(nqw, nkw, naqw, nakw, fcos, fsin);
    // joint flash attention
    attn_fa<<<dim3(S_TOT / 64, NH), 128, 128 * ROWPAD * 4>>>();
    // adapter attention + merge
    merge_adapter<<<dim3(S_TOT, NH), 128>>>(bscale);

    // output projections: d_out = [img_out (2048x3072), enc_out (512x3072)]
    gemm_tf32<<<dim3(DM / BN, S_IMG / BM), 256>>>(hs + (size_t)S_TXT * DM, Wo, bo,
                                                  out, S_IMG, DM);
    gemm_tf32<<<dim3(DM / BN, S_TXT / BM), 256>>>(hs, Woa, boa,
                                                  out + (size_t)S_IMG * DM,
                                                  S_TXT, DM);
}

// round 6
// speedup vs baseline: 4.2511x; 3.5616x over previous
#include <cuda_runtime.h>
#include <math.h>
#include <stdint.h>

#define S_IMG 2048
#define S_TXT 512
#define S_TOT 2560
#define DM    3072
#define NH    24
#define HD    128
#define ATOK  4
#define ADIM  1024
#define SM_SCALE 0.08838834764831845f  /* 1/sqrt(128) */

// ---------------- scratch (device globals; no allocation allowed) ----------------
__device__ float g_pq_img[(size_t)S_IMG * DM];
__device__ float g_pk_img[(size_t)S_IMG * DM];
__device__ float g_pv_img[(size_t)S_IMG * DM];
__device__ float g_pq_txt[(size_t)S_TXT * DM];
__device__ float g_pk_txt[(size_t)S_TXT * DM];
__device__ float g_pv_txt[(size_t)S_TXT * DM];
__device__ float g_q[(size_t)NH * S_TOT * HD];
__device__ float g_k[(size_t)NH * S_TOT * HD];
__device__ float g_v[(size_t)NH * S_TOT * HD];
__device__ float g_o[(size_t)NH * S_TOT * HD];
__device__ float g_hs[(size_t)S_TOT * DM];
__device__ float g_ka[ATOK * DM];
__device__ float g_va[ATOK * DM];

// ------------------------- tf32 helpers ----------------------------------------
__device__ __forceinline__ uint32_t f2tf32(float f) {
    uint32_t r;
    asm("cvt.rna.tf32.f32 %0, %1;" : "=r"(r) : "f"(f));
    return r;
}

__device__ __forceinline__ float4 cvt4(float4 v) {
    float4 t;
    t.x = __uint_as_float(f2tf32(v.x));
    t.y = __uint_as_float(f2tf32(v.y));
    t.z = __uint_as_float(f2tf32(v.z));
    t.w = __uint_as_float(f2tf32(v.w));
    return t;
}

__device__ __forceinline__ void mma_tf32(float4& d, const uint32_t a[4],
                                         const uint32_t b[2]) {
    asm volatile(
        "mma.sync.aligned.m16n8k8.row.col.f32.tf32.tf32.f32 "
        "{%0,%1,%2,%3}, {%4,%5,%6,%7}, {%8,%9}, {%0,%1,%2,%3};\n"
        : "+f"(d.x), "+f"(d.y), "+f"(d.z), "+f"(d.w)
        : "r"(a[0]), "r"(a[1]), "r"(a[2]), "r"(a[3]), "r"(b[0]), "r"(b[1]));
}

// --------- batched, double-buffered tf32 GEMM: C = A[M,K] @ W[K,3072] + bias -----
// blockIdx.z selects the problem from a pointer table. CTA tile 128x128, BK=16,
// 2-stage smem pipeline with register-staged prefetch.
#define BM 128
#define BN 128
#define BK 16
#define PADA 20    /* 20 mod 32 = 4: frag bank = 4*gid + tig, bijective */
#define PADB 136   /* frag bank = 8*tig + gid, bijective */

struct GB { const float* A; const float* W; const float* bias; float* C; int M; int K; };
struct GB6 { GB e[6]; };

__global__ __launch_bounds__(256, 2) void gemm_bt(GB6 ga)
{
    const GB g = ga.e[blockIdx.z];
    const int M = g.M, K = g.K;
    const int m0 = blockIdx.y * BM;
    if (m0 >= M) return;
    const int n0 = blockIdx.x * BN;

    __shared__ float As[2][BM][PADA];
    __shared__ float Bs[2][BK][PADB];

    const float* __restrict__ A = g.A;
    const float* __restrict__ W = g.W;
    const int tid  = threadIdx.x;
    const int warp = tid >> 5, lane = tid & 31;
    const int gid  = lane >> 2, tig = lane & 3;
    const int wm = (warp & 3) * 32;
    const int wn = (warp >> 2) * 64;

    const int ar = tid >> 2, ac = (tid & 3) * 4;    // A: rows ar, ar+64; cols ac..ac+3
    const int br = tid >> 5, bc = (tid & 31) * 4;   // B: rows br, br+8

    float4 acc[2][8];
    #pragma unroll
    for (int i = 0; i < 2; i++)
        #pragma unroll
        for (int j = 0; j < 8; j++) acc[i][j] = make_float4(0.f, 0.f, 0.f, 0.f);

    float4 ra0, ra1, rb0, rb1;
    // prologue: load k-tile 0
    ra0 = (m0 + ar      < M) ? *(const float4*)&A[(size_t)(m0 + ar     ) * K + ac]
                             : make_float4(0.f, 0.f, 0.f, 0.f);
    ra1 = (m0 + ar + 64 < M) ? *(const float4*)&A[(size_t)(m0 + ar + 64) * K + ac]
                             : make_float4(0.f, 0.f, 0.f, 0.f);
    rb0 = *(const float4*)&W[(size_t)(br    ) * DM + n0 + bc];
    rb1 = *(const float4*)&W[(size_t)(br + 8) * DM + n0 + bc];
    *(float4*)&As[0][ar     ][ac] = cvt4(ra0);
    *(float4*)&As[0][ar + 64][ac] = cvt4(ra1);
    *(float4*)&Bs[0][br    ][bc] = cvt4(rb0);
    *(float4*)&Bs[0][br + 8][bc] = cvt4(rb1);

    const int nIters = K / BK;
    for (int it = 0; it < nIters; it++) {
        const int st = it & 1;
        __syncthreads();
        const bool hasNext = (it + 1 < nIters);
        if (hasNext) {
            const int k0n = (it + 1) * BK;
            ra0 = (m0 + ar      < M) ? *(const float4*)&A[(size_t)(m0 + ar     ) * K + k0n + ac]
                                     : make_float4(0.f, 0.f, 0.f, 0.f);
            ra1 = (m0 + ar + 64 < M) ? *(const float4*)&A[(size_t)(m0 + ar + 64) * K + k0n + ac]
                                     : make_float4(0.f, 0.f, 0.f, 0.f);
            rb0 = *(const float4*)&W[(size_t)(k0n + br    ) * DM + n0 + bc];
            rb1 = *(const float4*)&W[(size_t)(k0n + br + 8) * DM + n0 + bc];
        }
        // compute current stage
        #pragma unroll
        for (int kk = 0; kk < BK; kk += 8) {
            uint32_t af[2][4];
            #pragma unroll
            for (int mt = 0; mt < 2; mt++) {
                int r = wm + mt * 16 + gid;
                af[mt][0] = __float_as_uint(As[st][r    ][kk + tig]);
                af[mt][1] = __float_as_uint(As[st][r + 8][kk + tig]);
                af[mt][2] = __float_as_uint(As[st][r    ][kk + tig + 4]);
                af[mt][3] = __float_as_uint(As[st][r + 8][kk + tig + 4]);
            }
            uint32_t bf[8][2];
            #pragma unroll
            for (int nt = 0; nt < 8; nt++) {
                int c = wn + nt * 8 + gid;
                bf[nt][0] = __float_as_uint(Bs[st][kk + tig    ][c]);
                bf[nt][1] = __float_as_uint(Bs[st][kk + tig + 4][c]);
            }
            #pragma unroll
            for (int mt = 0; mt < 2; mt++)
                #pragma unroll
                for (int nt = 0; nt < 8; nt++)
                    mma_tf32(acc[mt][nt], af[mt], bf[nt]);
        }
        if (hasNext) {
            const int ns = st ^ 1;
            *(float4*)&As[ns][ar     ][ac] = cvt4(ra0);
            *(float4*)&As[ns][ar + 64][ac] = cvt4(ra1);
            *(float4*)&Bs[ns][br    ][bc] = cvt4(rb0);
            *(float4*)&Bs[ns][br + 8][bc] = cvt4(rb1);
        }
    }

    const float* bias = g.bias;
    float* C = g.C;
    #pragma unroll
    for (int mt = 0; mt < 2; mt++) {
        int r0 = m0 + wm + mt * 16 + gid;
        #pragma unroll
        for (int nt = 0; nt < 8; nt++) {
            int col = n0 + wn + nt * 8 + tig * 2;
            float b0 = bias ? bias[col] : 0.f;
            float b1 = bias ? bias[col + 1] : 0.f;
            if (r0 < M) {
                *(float2*)&C[(size_t)r0 * DM + col] =
                    make_float2(acc[mt][nt].x + b0, acc[mt][nt].y + b1);
            }
            if (r0 + 8 < M) {
                *(float2*)&C[(size_t)(r0 + 8) * DM + col] =
                    make_float2(acc[mt][nt].z + b0, acc[mt][nt].w + b1);
            }
        }
    }
}

// ------------- RMSNorm + RoPE + concat into [H, S_TOT, HD] --------------------
__global__ __launch_bounds__(128) void qkv_transform(
    const float* __restrict__ nqw, const float* __restrict__ nkw,
    const float* __restrict__ naqw, const float* __restrict__ nakw,
    const float* __restrict__ fcos, const float* __restrict__ fsin)
{
    const int s = blockIdx.x, h = blockIdx.y, d = threadIdx.x;
    const int lane = d & 31, wid = d >> 5;
    __shared__ float ws[4];
    const bool txt = s < S_TXT;
    const size_t roff = txt ? (size_t)s * DM : (size_t)(s - S_TXT) * DM;
    const size_t col = roff + h * HD + d;
    const float* xq = txt ? g_pq_txt : g_pq_img;
    const float* xk = txt ? g_pk_txt : g_pk_img;
    const float* xv = txt ? g_pv_txt : g_pv_img;
    const float wq = txt ? naqw[d] : nqw[d];
    const float wk = txt ? nakw[d] : nkw[d];
    const float c = fcos[s * HD + d];
    const float sn = fsin[s * HD + d];
    const size_t oidx = ((size_t)h * S_TOT + s) * HD + d;

    float q = xq[col];
    float t2 = q * q;
    #pragma unroll
    for (int off = 16; off; off >>= 1) t2 += __shfl_xor_sync(0xffffffffu, t2, off);
    if (lane == 0) ws[wid] = t2;
    __syncthreads();
    float tot = ws[0] + ws[1] + ws[2] + ws[3];
    float qn = q * rsqrtf(tot * (1.f / HD) + 1e-6f) * wq;
    float pq = __shfl_xor_sync(0xffffffffu, qn, 1);
    float rotq = (d & 1) ? pq : -pq;
    g_q[oidx] = qn * c + rotq * sn;
    __syncthreads();

    float k = xk[col];
    t2 = k * k;
    #pragma unroll
    for (int off = 16; off; off >>= 1) t2 += __shfl_xor_sync(0xffffffffu, t2, off);
    if (lane == 0) ws[wid] = t2;
    __syncthreads();
    tot = ws[0] + ws[1] + ws[2] + ws[3];
    float kn = k * rsqrtf(tot * (1.f / HD) + 1e-6f) * wk;
    float pk = __shfl_xor_sync(0xffffffffu, kn, 1);
    float rotk = (d & 1) ? pk : -pk;
    g_k[oidx] = kn * c + rotk * sn;

    g_v[oidx] = xv[col];
}

// ---------------- tensor-core flash attention (tf32 mma) -----------------------
// BQ=128 rows/CTA, 8 warps (16 rows each), BKV=64 keys/tile.
#define AQ 128
#define AKV 64
#define QPAD 132   /* 132 mod 32 = 4: [row][k] frag reads conflict-free */
#define VPAD 136   /* 136 mod 32 = 8: [k][col] frag reads conflict-free */
#define ATTN_SMEM ((AQ * QPAD + AKV * QPAD + AKV * VPAD) * 4)

__global__ __launch_bounds__(256) void attn_mma()
{
    extern __shared__ float sm[];
    float* Qs = sm;                       // [128][132] tf32, pre-scaled
    float* Ks = Qs + AQ * QPAD;           // [64][132] tf32
    float* Vs = Ks + AKV * QPAD;          // [64][136] tf32
    const int qt = blockIdx.x, h = blockIdx.y;
    const int tid = threadIdx.x;
    const int warp = tid >> 5, lane = tid & 31;
    const int gid = lane >> 2, tig = lane & 3;
    const int wm = warp * 16;

    const float* Qg = g_q + ((size_t)h * S_TOT + qt * AQ) * HD;
    const float* Kg = g_k + (size_t)h * S_TOT * HD;
    const float* Vg = g_v + (size_t)h * S_TOT * HD;

    // load + scale + tf32-convert Q
    for (int i = tid; i < AQ * (HD / 4); i += 256) {
        int r = i >> 5, c = (i & 31) * 4;
        float4 v = *(const float4*)&Qg[(size_t)r * HD + c];
        Qs[r * QPAD + c + 0] = __uint_as_float(f2tf32(v.x * SM_SCALE));
        Qs[r * QPAD + c + 1] = __uint_as_float(f2tf32(v.y * SM_SCALE));
        Qs[r * QPAD + c + 2] = __uint_as_float(f2tf32(v.z * SM_SCALE));
        Qs[r * QPAD + c + 3] = __uint_as_float(f2tf32(v.w * SM_SCALE));
    }

    float m0 = -1e30f, m1 = -1e30f, l0 = 0.f, l1 = 0.f;
    float4 o[16];
    #pragma unroll
    for (int i = 0; i < 16; i++) o[i] = make_float4(0.f, 0.f, 0.f, 0.f);

    for (int kt = 0; kt < S_TOT / AKV; kt++) {
        __syncthreads();
        const float* Kt = Kg + (size_t)kt * AKV * HD;
        const float* Vt = Vg + (size_t)kt * AKV * HD;
        for (int i = tid; i < AKV * (HD / 4); i += 256) {
            int r = i >> 5, c = (i & 31) * 4;
            float4 kv = *(const float4*)&Kt[(size_t)r * HD + c];
            Ks[r * QPAD + c + 0] = __uint_as_float(f2tf32(kv.x));
            Ks[r * QPAD + c + 1] = __uint_as_float(f2tf32(kv.y));
            Ks[r * QPAD + c + 2] = __uint_as_float(f2tf32(kv.z));
            Ks[r * QPAD + c + 3] = __uint_as_float(f2tf32(kv.w));
            float4 vv = *(const float4*)&Vt[(size_t)r * HD + c];
            Vs[r * VPAD + c + 0] = __uint_as_float(f2tf32(vv.x));
            Vs[r * VPAD + c + 1] = __uint_as_float(f2tf32(vv.y));
            Vs[r * VPAD + c + 2] = __uint_as_float(f2tf32(vv.z));
            Vs[r * VPAD + c + 3] = __uint_as_float(f2tf32(vv.w));
        }
        __syncthreads();

        // S = Q @ K^T : 16 x 64 per warp
        float4 s[8];
        #pragma unroll
        for (int nb = 0; nb < 8; nb++) s[nb] = make_float4(0.f, 0.f, 0.f, 0.f);
        #pragma unroll
        for (int ks = 0; ks < HD / 8; ks++) {
            const int kk = ks * 8;
            uint32_t a[4];
            a[0] = __float_as_uint(Qs[(wm + gid    ) * QPAD + kk + tig]);
            a[1] = __float_as_uint(Qs[(wm + gid + 8) * QPAD + kk + tig]);
            a[2] = __float_as_uint(Qs[(wm + gid    ) * QPAD + kk + tig + 4]);
            a[3] = __float_as_uint(Qs[(wm + gid + 8) * QPAD + kk + tig + 4]);
            #pragma unroll
            for (int nb = 0; nb < 8; nb++) {
                uint32_t b[2];
                b[0] = __float_as_uint(Ks[(nb * 8 + gid) * QPAD + kk + tig]);
                b[1] = __float_as_uint(Ks[(nb * 8 + gid) * QPAD + kk + tig + 4]);
                mma_tf32(s[nb], a, b);
            }
        }

        // online softmax (rows gid -> .x/.y, gid+8 -> .z/.w)
        float mx0 = m0, mx1 = m1;
        #pragma unroll
        for (int nb = 0; nb < 8; nb++) {
            mx0 = fmaxf(mx0, fmaxf(s[nb].x, s[nb].y));
            mx1 = fmaxf(mx1, fmaxf(s[nb].z, s[nb].w));
        }
        mx0 = fmaxf(mx0, __shfl_xor_sync(0xffffffffu, mx0, 1));
        mx0 = fmaxf(mx0, __shfl_xor_sync(0xffffffffu, mx0, 2));
        mx1 = fmaxf(mx1, __shfl_xor_sync(0xffffffffu, mx1, 1));
        mx1 = fmaxf(mx1, __shfl_xor_sync(0xffffffffu, mx1, 2));
        const float c0 = __expf(m0 - mx0);
        const float c1 = __expf(m1 - mx1);
        m0 = mx0; m1 = mx1;
        float ls0 = 0.f, ls1 = 0.f;
        #pragma unroll
        for (int nb = 0; nb < 8; nb++) {
            s[nb].x = __expf(s[nb].x - m0);
            s[nb].y = __expf(s[nb].y - m0);
            s[nb].z = __expf(s[nb].z - m1);
            s[nb].w = __expf(s[nb].w - m1);
            ls0 += s[nb].x + s[nb].y;
            ls1 += s[nb].z + s[nb].w;
        }
        l0 = l0 * c0 + ls0;
        l1 = l1 * c1 + ls1;
        #pragma unroll
        for (int i = 0; i < 16; i++) {
            o[i].x *= c0; o[i].y *= c0; o[i].z *= c1; o[i].w *= c1;
        }

        // O += P @ V.  P A-frags built from S C-frags via quad shuffles.
        const int srcA = (lane & ~3) | (tig >> 1);
        const int srcB = srcA + 2;
        #pragma unroll
        for (int kb = 0; kb < 8; kb++) {
            float xA = __shfl_sync(0xffffffffu, s[kb].x, srcA);
            float yA = __shfl_sync(0xffffffffu, s[kb].y, srcA);
            float zA = __shfl_sync(0xffffffffu, s[kb].z, srcA);
            float wA = __shfl_sync(0xffffffffu, s[kb].w, srcA);
            float xB = __shfl_sync(0xffffffffu, s[kb].x, srcB);
            float yB = __shfl_sync(0xffffffffu, s[kb].y, srcB);
            float zB = __shfl_sync(0xffffffffu, s[kb].z, srcB);
            float wB = __shfl_sync(0xffffffffu, s[kb].w, srcB);
            uint32_t a[4];
            a[0] = f2tf32((tig & 1) ? yA : xA);
            a[1] = f2tf32((tig & 1) ? wA : zA);
            a[2] = f2tf32((tig & 1) ? yB : xB);
            a[3] = f2tf32((tig & 1) ? wB : zB);
            #pragma unroll
            for (int nb = 0; nb < 16; nb++) {
                uint32_t b[2];
                b[0] = __float_as_uint(Vs[(kb * 8 + tig    ) * VPAD + nb * 8 + gid]);
                b[1] = __float_as_uint(Vs[(kb * 8 + tig + 4) * VPAD + nb * 8 + gid]);
                mma_tf32(o[nb], a, b);
            }
        }
    }

    l0 += __shfl_xor_sync(0xffffffffu, l0, 1);
    l0 += __shfl_xor_sync(0xffffffffu, l0, 2);
    l1 += __shfl_xor_sync(0xffffffffu, l1, 1);
    l1 += __shfl_xor_sync(0xffffffffu, l1, 2);
    const float i0 = 1.f / l0, i1 = 1.f / l1;

    const int r0 = qt * AQ + wm + gid;
    float* O0 = g_o + ((size_t)h * S_TOT + r0) * HD;
    float* O1 = O0 + 8 * HD;
    #pragma unroll
    for (int nb = 0; nb < 16; nb++) {
        int col = nb * 8 + tig * 2;
        *(float2*)&O0[col] = make_float2(o[nb].x * i0, o[nb].y * i0);
        *(float2*)&O1[col] = make_float2(o[nb].z * i1, o[nb].w * i1);
    }
}

// ------- adapter 4-key cross-attention + merge into [S_TOT, DM] ----------------
__global__ __launch_bounds__(128) void merge_adapter(const float* __restrict__ bscale)
{
    const int s = blockIdx.x, h = blockIdx.y, d = threadIdx.x;
    const int lane = d & 31, wid = d >> 5;
    __shared__ float wsum[4];
    __shared__ float sd[4];
    const size_t qidx = ((size_t)h * S_TOT + s) * HD + d;
    const float qv = g_q[qidx];
    const int hcol = h * HD + d;
    #pragma unroll
    for (int t = 0; t < ATOK; t++) {
        float p = qv * g_ka[t * DM + hcol];
        #pragma unroll
        for (int off = 16; off; off >>= 1) p += __shfl_xor_sync(0xffffffffu, p, off);
        if (lane == 0) wsum[wid] = p;
        __syncthreads();
        if (d == 0) sd[t] = (wsum[0] + wsum[1] + wsum[2] + wsum[3]) * SM_SCALE;
        __syncthreads();
    }
    float d0 = sd[0], d1 = sd[1], d2 = sd[2], d3 = sd[3];
    float mx = fmaxf(fmaxf(d0, d1), fmaxf(d2, d3));
    float e0 = __expf(d0 - mx), e1 = __expf(d1 - mx);
    float e2 = __expf(d2 - mx), e3 = __expf(d3 - mx);
    float inv = 1.f / (e0 + e1 + e2 + e3);
    float vd = (e0 * g_va[0 * DM + hcol] + e1 * g_va[1 * DM + hcol] +
                e2 * g_va[2 * DM + hcol] + e3 * g_va[3 * DM + hcol]) * inv;
    g_hs[(size_t)s * DM + hcol] = g_o[qidx] + bscale[0] * vd;
}

// -------------------------------- launch ---------------------------------------
extern "C" void kernel_launch(void* const* d_in, const int* in_sizes, int n_in,
                              void* d_out, int out_size)
{
    const float* hidden = (const float*)d_in[0];
    const float* enc    = (const float*)d_in[1];
    const float* adapt  = (const float*)d_in[2];
    const float* fcos   = (const float*)d_in[3];
    const float* fsin   = (const float*)d_in[4];
    const float* Wq  = (const float*)d_in[5];  const float* bq  = (const float*)d_in[6];
    const float* Wk  = (const float*)d_in[7];  const float* bk  = (const float*)d_in[8];
    const float* Wv  = (const float*)d_in[9];  const float* bv  = (const float*)d_in[10];
    const float* nqw = (const float*)d_in[11]; const float* nkw = (const float*)d_in[12];
    const float* Wqa = (const float*)d_in[13]; const float* bqa = (const float*)d_in[14];
    const float* Wka = (const float*)d_in[15]; const float* bka = (const float*)d_in[16];
    const float* Wva = (const float*)d_in[17]; const float* bva = (const float*)d_in[18];
    const float* naqw = (const float*)d_in[19]; const float* nakw = (const float*)d_in[20];
    const float* Wo  = (const float*)d_in[21]; const float* bo  = (const float*)d_in[22];
    const float* Woa = (const float*)d_in[23]; const float* boa = (const float*)d_in[24];
    const float* Wkad = (const float*)d_in[25]; const float* Wvad = (const float*)d_in[26];
    const float* bscale = (const float*)d_in[27];
    float* out = (float*)d_out;

    float *pq_img, *pk_img, *pv_img, *pq_txt, *pk_txt, *pv_txt, *ka, *va, *hs;
    cudaGetSymbolAddress((void**)&pq_img, g_pq_img);
    cudaGetSymbolAddress((void**)&pk_img, g_pk_img);
    cudaGetSymbolAddress((void**)&pv_img, g_pv_img);
    cudaGetSymbolAddress((void**)&pq_txt, g_pq_txt);
    cudaGetSymbolAddress((void**)&pk_txt, g_pk_txt);
    cudaGetSymbolAddress((void**)&pv_txt, g_pv_txt);
    cudaGetSymbolAddress((void**)&ka, g_ka);
    cudaGetSymbolAddress((void**)&va, g_va);
    cudaGetSymbolAddress((void**)&hs, g_hs);

    cudaFuncSetAttribute(attn_mma, cudaFuncAttributeMaxDynamicSharedMemorySize,
                         ATTN_SMEM);

    // --- all 6 QKV projections in one launch ---
    GB6 qkv;
    qkv.e[0] = { hidden, Wq,  bq,  pq_img, S_IMG, DM };
    qkv.e[1] = { hidden, Wk,  bk,  pk_img, S_IMG, DM };
    qkv.e[2] = { hidden, Wv,  bv,  pv_img, S_IMG, DM };
    qkv.e[3] = { enc,    Wqa, bqa, pq_txt, S_TXT, DM };
    qkv.e[4] = { enc,    Wka, bka, pk_txt, S_TXT, DM };
    qkv.e[5] = { enc,    Wva, bva, pv_txt, S_TXT, DM };
    gemm_bt<<<dim3(DM / BN, S_IMG / BM, 6), 256>>>(qkv);

    // --- adapter K/V (M=4, K=1024) ---
    GB6 ad;
    ad.e[0] = { adapt, Wkad, (const float*)0, ka, ATOK, ADIM };
    ad.e[1] = { adapt, Wvad, (const float*)0, va, ATOK, ADIM };
    ad.e[2] = ad.e[0]; ad.e[2].M = 0;
    ad.e[3] = ad.e[0]; ad.e[3].M = 0;
    ad.e[4] = ad.e[0]; ad.e[4].M = 0;
    ad.e[5] = ad.e[0]; ad.e[5].M = 0;
    gemm_bt<<<dim3(DM / BN, 1, 2), 256>>>(ad);

    // RMSNorm + RoPE + head layout
    qkv_transform<<<dim3(S_TOT, NH), 128>>>(nqw, nkw, naqw, nakw, fcos, fsin);
    // joint flash attention (tf32 tensor cores)
    attn_mma<<<dim3(S_TOT / AQ, NH), 256, ATTN_SMEM>>>();
    // adapter attention + merge
    merge_adapter<<<dim3(S_TOT, NH), 128>>>(bscale);

    // --- both output projections in one launch ---
    GB6 op;
    op.e[0] = { hs + (size_t)S_TXT * DM, Wo,  bo,  out,                        S_IMG, DM };
    op.e[1] = { hs,                      Woa, boa, out + (size_t)S_IMG * DM,   S_TXT, DM };
    op.e[2] = op.e[0]; op.e[2].M = 0;
    op.e[3] = op.e[0]; op.e[3].M = 0;
    op.e[4] = op.e[0]; op.e[4].M = 0;
    op.e[5] = op.e[0]; op.e[5].M = 0;
    gemm_bt<<<dim3(DM / BN, S_IMG / BM, 2), 256>>>(op);
}

// round 7
// speedup vs baseline: 5.4654x; 1.2857x over previous
#include <cuda_runtime.h>
#include <math.h>
#include <stdint.h>

#define S_IMG 2048
#define S_TXT 512
#define S_TOT 2560
#define DM    3072
#define NH    24
#define HD    128
#define ATOK  4
#define ADIM  1024
#define SM_SCALE 0.08838834764831845f  /* 1/sqrt(128) */

// ---------------- scratch (device globals; no allocation allowed) ----------------
__device__ float g_pq_img[(size_t)S_IMG * DM];
__device__ float g_pk_img[(size_t)S_IMG * DM];
__device__ float g_pv_img[(size_t)S_IMG * DM];
__device__ float g_pq_txt[(size_t)S_TXT * DM];
__device__ float g_pk_txt[(size_t)S_TXT * DM];
__device__ float g_pv_txt[(size_t)S_TXT * DM];
__device__ float g_q[(size_t)NH * S_TOT * HD];
__device__ float g_k[(size_t)NH * S_TOT * HD];
__device__ float g_v[(size_t)NH * S_TOT * HD];
__device__ float g_o[(size_t)NH * S_TOT * HD];
__device__ float g_hs[(size_t)S_TOT * DM];
__device__ float g_ka[ATOK * DM];
__device__ float g_va[ATOK * DM];
// tf32-pre-rounded copies (exact-truncation path for mma)
__device__ float g_chid[(size_t)S_IMG * DM];
__device__ float g_cenc[(size_t)S_TXT * DM];
__device__ float g_cad[ATOK * ADIM];
__device__ float g_cWq[(size_t)DM * DM];
__device__ float g_cWk[(size_t)DM * DM];
__device__ float g_cWv[(size_t)DM * DM];
__device__ float g_cWqa[(size_t)DM * DM];
__device__ float g_cWka[(size_t)DM * DM];
__device__ float g_cWva[(size_t)DM * DM];
__device__ float g_cWo[(size_t)DM * DM];
__device__ float g_cWoa[(size_t)DM * DM];
__device__ float g_cWkad[(size_t)ADIM * DM];
__device__ float g_cWvad[(size_t)ADIM * DM];

// ------------------------- helpers ----------------------------------------------
__device__ __forceinline__ uint32_t f2tf32(float f) {
    uint32_t r;
    asm("cvt.rna.tf32.f32 %0, %1;" : "=r"(r) : "f"(f));
    return r;
}
__device__ __forceinline__ float tf32r(float f) { return __uint_as_float(f2tf32(f)); }
__device__ __forceinline__ float4 cvt4(float4 v) {
    return make_float4(tf32r(v.x), tf32r(v.y), tf32r(v.z), tf32r(v.w));
}
__device__ __forceinline__ void mma_tf32(float4& d, const uint32_t a[4],
                                         const uint32_t b[2]) {
    asm volatile(
        "mma.sync.aligned.m16n8k8.row.col.f32.tf32.tf32.f32 "
        "{%0,%1,%2,%3}, {%4,%5,%6,%7}, {%8,%9}, {%0,%1,%2,%3};\n"
        : "+f"(d.x), "+f"(d.y), "+f"(d.z), "+f"(d.w)
        : "r"(a[0]), "r"(a[1]), "r"(a[2]), "r"(a[3]), "r"(b[0]), "r"(b[1]));
}
#define CPA16(dst, src, pb) \
    asm volatile("cp.async.cg.shared.global [%0], [%1], 16, %2;\n" \
                 :: "r"(dst), "l"(src), "r"(pb))
#define CPCOMMIT() asm volatile("cp.async.commit_group;\n" ::)
#define CPWAIT(n)  asm volatile("cp.async.wait_group %0;\n" :: "n"(n))

// ------------------------- pre-round pass ----------------------------------------
struct CV { const float* s; float* d; int n; };
struct CV13 { CV e[13]; };
__global__ __launch_bounds__(256) void prep_cvt(CV13 t)
{
    const CV c = t.e[blockIdx.y];
    int idx = (blockIdx.x * 256 + threadIdx.x) * 4;
    if (idx < c.n)
        *(float4*)&c.d[idx] = cvt4(*(const float4*)&c.s[idx]);
}

// --------- batched cp.async tf32 GEMM: C = A[M,K] @ W[K,3072] + bias -------------
// 3-stage pipeline, CTA tile 128x128, BK=32. A/W must be pre-rounded to tf32.
#define BM 128
#define BN 128
#define BKG 32
#define PA 36     /* frag bank = 4*gid + tig (+4k per kk), bijective */
#define PB 136    /* frag bank = 8*tig + gid, bijective */
#define GSTAGE (BM * PA + BKG * PB)        /* floats per stage = 8960 */
#define GSMEM  (3 * GSTAGE * 4)            /* 107520 B */

struct GB { const float* A; const float* W; const float* bias; float* C; int M; int K; };
struct GB6 { GB e[6]; };

__global__ __launch_bounds__(256, 2) void gemm_ca(GB6 ga)
{
    const GB g = ga.e[blockIdx.z];
    const int M = g.M, K = g.K;
    const int m0 = blockIdx.y * BM;
    if (m0 >= M) return;
    const int n0 = blockIdx.x * BN;

    extern __shared__ float smg[];
    const float* __restrict__ A = g.A;
    const float* __restrict__ W = g.W;
    const int tid  = threadIdx.x;
    const int warp = tid >> 5, lane = tid & 31;
    const int gid  = lane >> 2, tig = lane & 3;
    const int wm = (warp & 3) * 32;
    const int wn = (warp >> 2) * 64;

    // loader mapping: A tile 128x32 floats = 1024 16B-chunks, 4/thread
    //                 B tile 32x128 floats = 1024 chunks, 4/thread
    const int nIters = K / BKG;

    auto issue_tile = [&](int it, int stage) {
        float* As = smg + stage * GSTAGE;
        float* Bs = As + BM * PA;
        const int k0 = it * BKG;
        #pragma unroll
        for (int i = 0; i < 4; i++) {
            int c = tid + i * 256;
            int r = c >> 3, col = (c & 7) * 4;
            uint32_t dst = (uint32_t)__cvta_generic_to_shared(&As[r * PA + col]);
            const float* src = &A[(size_t)(m0 + r) * K + k0 + col];
            CPA16(dst, src, (m0 + r < M) ? 16 : 0);
        }
        #pragma unroll
        for (int i = 0; i < 4; i++) {
            int c = tid + i * 256;
            int r = c >> 5, col = (c & 31) * 4;
            uint32_t dst = (uint32_t)__cvta_generic_to_shared(&Bs[r * PB + col]);
            const float* src = &W[(size_t)(k0 + r) * DM + n0 + col];
            CPA16(dst, src, 16);
        }
        CPCOMMIT();
    };

    float4 acc[2][8];
    #pragma unroll
    for (int i = 0; i < 2; i++)
        #pragma unroll
        for (int j = 0; j < 8; j++) acc[i][j] = make_float4(0.f, 0.f, 0.f, 0.f);

    issue_tile(0, 0);
    if (nIters > 1) issue_tile(1, 1);

    for (int it = 0; it < nIters; it++) {
        if (it + 1 < nIters) { CPWAIT(1); } else { CPWAIT(0); }
        __syncthreads();
        if (it + 2 < nIters) issue_tile(it + 2, (it + 2) % 3);

        const float* As = smg + (it % 3) * GSTAGE;
        const float* Bs = As + BM * PA;
        #pragma unroll
        for (int kk = 0; kk < BKG; kk += 8) {
            uint32_t af[2][4];
            #pragma unroll
            for (int mt = 0; mt < 2; mt++) {
                int r = wm + mt * 16 + gid;
                af[mt][0] = __float_as_uint(As[(r    ) * PA + kk + tig]);
                af[mt][1] = __float_as_uint(As[(r + 8) * PA + kk + tig]);
                af[mt][2] = __float_as_uint(As[(r    ) * PA + kk + tig + 4]);
                af[mt][3] = __float_as_uint(As[(r + 8) * PA + kk + tig + 4]);
            }
            uint32_t bf[8][2];
            #pragma unroll
            for (int nt = 0; nt < 8; nt++) {
                int c = wn + nt * 8 + gid;
                bf[nt][0] = __float_as_uint(Bs[(kk + tig    ) * PB + c]);
                bf[nt][1] = __float_as_uint(Bs[(kk + tig + 4) * PB + c]);
            }
            #pragma unroll
            for (int mt = 0; mt < 2; mt++)
                #pragma unroll
                for (int nt = 0; nt < 8; nt++)
                    mma_tf32(acc[mt][nt], af[mt], bf[nt]);
        }
        __syncthreads();
    }

    const float* bias = g.bias;
    float* C = g.C;
    #pragma unroll
    for (int mt = 0; mt < 2; mt++) {
        int r0 = m0 + wm + mt * 16 + gid;
        #pragma unroll
        for (int nt = 0; nt < 8; nt++) {
            int col = n0 + wn + nt * 8 + tig * 2;
            float b0 = bias ? bias[col] : 0.f;
            float b1 = bias ? bias[col + 1] : 0.f;
            if (r0 < M)
                *(float2*)&C[(size_t)r0 * DM + col] =
                    make_float2(acc[mt][nt].x + b0, acc[mt][nt].y + b1);
            if (r0 + 8 < M)
                *(float2*)&C[(size_t)(r0 + 8) * DM + col] =
                    make_float2(acc[mt][nt].z + b0, acc[mt][nt].w + b1);
        }
    }
}

// ------------- RMSNorm + RoPE -> tf32-rounded [H, S_TOT, HD] --------------------
// q is additionally pre-scaled by SM_SCALE.
__global__ __launch_bounds__(128) void qkv_transform(
    const float* __restrict__ nqw, const float* __restrict__ nkw,
    const float* __restrict__ naqw, const float* __restrict__ nakw,
    const float* __restrict__ fcos, const float* __restrict__ fsin)
{
    const int s = blockIdx.x, h = blockIdx.y, d = threadIdx.x;
    const int lane = d & 31, wid = d >> 5;
    __shared__ float ws[4];
    const bool txt = s < S_TXT;
    const size_t roff = txt ? (size_t)s * DM : (size_t)(s - S_TXT) * DM;
    const size_t col = roff + h * HD + d;
    const float* xq = txt ? g_pq_txt : g_pq_img;
    const float* xk = txt ? g_pk_txt : g_pk_img;
    const float* xv = txt ? g_pv_txt : g_pv_img;
    const float wq = txt ? naqw[d] : nqw[d];
    const float wk = txt ? nakw[d] : nkw[d];
    const float c = fcos[s * HD + d];
    const float sn = fsin[s * HD + d];
    const size_t oidx = ((size_t)h * S_TOT + s) * HD + d;

    float q = xq[col];
    float t2 = q * q;
    #pragma unroll
    for (int off = 16; off; off >>= 1) t2 += __shfl_xor_sync(0xffffffffu, t2, off);
    if (lane == 0) ws[wid] = t2;
    __syncthreads();
    float tot = ws[0] + ws[1] + ws[2] + ws[3];
    float qn = q * rsqrtf(tot * (1.f / HD) + 1e-6f) * wq;
    float pq = __shfl_xor_sync(0xffffffffu, qn, 1);
    float rotq = (d & 1) ? pq : -pq;
    g_q[oidx] = tf32r((qn * c + rotq * sn) * SM_SCALE);
    __syncthreads();

    float k = xk[col];
    t2 = k * k;
    #pragma unroll
    for (int off = 16; off; off >>= 1) t2 += __shfl_xor_sync(0xffffffffu, t2, off);
    if (lane == 0) ws[wid] = t2;
    __syncthreads();
    tot = ws[0] + ws[1] + ws[2] + ws[3];
    float kn = k * rsqrtf(tot * (1.f / HD) + 1e-6f) * wk;
    float pk = __shfl_xor_sync(0xffffffffu, kn, 1);
    float rotk = (d & 1) ? pk : -pk;
    g_k[oidx] = tf32r(kn * c + rotk * sn);

    g_v[oidx] = tf32r(xv[col]);
}

// ---------------- tensor-core flash attention, cp.async double-buffered ---------
#define AQ 128
#define AKV 64
#define QPAD 132
#define VPAD 136
#define OFF_K(st) (AQ * QPAD + (st) * (AKV * QPAD))
#define OFF_V(st) (AQ * QPAD + 2 * (AKV * QPAD) + (st) * (AKV * VPAD))
#define ATTN_SMEM ((AQ * QPAD + 2 * AKV * QPAD + 2 * AKV * VPAD) * 4)

__global__ __launch_bounds__(256) void attn_mma()
{
    extern __shared__ float sm[];
    const int qt = blockIdx.x, h = blockIdx.y;
    const int tid = threadIdx.x;
    const int warp = tid >> 5, lane = tid & 31;
    const int gid = lane >> 2, tig = lane & 3;
    const int wm = warp * 16;

    const float* Qg = g_q + ((size_t)h * S_TOT + qt * AQ) * HD;
    const float* Kg = g_k + (size_t)h * S_TOT * HD;
    const float* Vg = g_v + (size_t)h * S_TOT * HD;

    auto issue_kv = [&](int kt, int st) {
        float* Ks = sm + OFF_K(st);
        float* Vs = sm + OFF_V(st);
        const float* Kt = Kg + (size_t)kt * AKV * HD;
        const float* Vt = Vg + (size_t)kt * AKV * HD;
        #pragma unroll
        for (int i = 0; i < 8; i++) {
            int c = tid + i * 256;               // 2048 chunks
            int r = c >> 5, col = (c & 31) * 4;
            uint32_t dk = (uint32_t)__cvta_generic_to_shared(&Ks[r * QPAD + col]);
            CPA16(dk, &Kt[(size_t)r * HD + col], 16);
            uint32_t dv = (uint32_t)__cvta_generic_to_shared(&Vs[r * VPAD + col]);
            CPA16(dv, &Vt[(size_t)r * HD + col], 16);
        }
    };

    // prologue: Q + KV tile 0 in one group
    {
        #pragma unroll
        for (int i = 0; i < 16; i++) {
            int c = tid + i * 256;               // 4096 chunks
            int r = c >> 5, col = (c & 31) * 4;
            uint32_t dq = (uint32_t)__cvta_generic_to_shared(&sm[r * QPAD + col]);
            CPA16(dq, &Qg[(size_t)r * HD + col], 16);
        }
        issue_kv(0, 0);
        CPCOMMIT();
    }

    float m0 = -1e30f, m1 = -1e30f, l0 = 0.f, l1 = 0.f;
    float4 o[16];
    #pragma unroll
    for (int i = 0; i < 16; i++) o[i] = make_float4(0.f, 0.f, 0.f, 0.f);

    const float* Qs = sm;
    for (int kt = 0; kt < S_TOT / AKV; kt++) {
        const int st = kt & 1;
        CPWAIT(0);
        __syncthreads();
        if (kt + 1 < S_TOT / AKV) { issue_kv(kt + 1, st ^ 1); CPCOMMIT(); }

        const float* Ks = sm + OFF_K(st);
        const float* Vs = sm + OFF_V(st);

        // S = Qs @ Ks^T : 16 x 64 per warp
        float4 s[8];
        #pragma unroll
        for (int nb = 0; nb < 8; nb++) s[nb] = make_float4(0.f, 0.f, 0.f, 0.f);
        #pragma unroll
        for (int ks = 0; ks < HD / 8; ks++) {
            const int kk = ks * 8;
            uint32_t a[4];
            a[0] = __float_as_uint(Qs[(wm + gid    ) * QPAD + kk + tig]);
            a[1] = __float_as_uint(Qs[(wm + gid + 8) * QPAD + kk + tig]);
            a[2] = __float_as_uint(Qs[(wm + gid    ) * QPAD + kk + tig + 4]);
            a[3] = __float_as_uint(Qs[(wm + gid + 8) * QPAD + kk + tig + 4]);
            #pragma unroll
            for (int nb = 0; nb < 8; nb++) {
                uint32_t b[2];
                b[0] = __float_as_uint(Ks[(nb * 8 + gid) * QPAD + kk + tig]);
                b[1] = __float_as_uint(Ks[(nb * 8 + gid) * QPAD + kk + tig + 4]);
                mma_tf32(s[nb], a, b);
            }
        }

        // online softmax
        float mx0 = m0, mx1 = m1;
        #pragma unroll
        for (int nb = 0; nb < 8; nb++) {
            mx0 = fmaxf(mx0, fmaxf(s[nb].x, s[nb].y));
            mx1 = fmaxf(mx1, fmaxf(s[nb].z, s[nb].w));
        }
        mx0 = fmaxf(mx0, __shfl_xor_sync(0xffffffffu, mx0, 1));
        mx0 = fmaxf(mx0, __shfl_xor_sync(0xffffffffu, mx0, 2));
        mx1 = fmaxf(mx1, __shfl_xor_sync(0xffffffffu, mx1, 1));
        mx1 = fmaxf(mx1, __shfl_xor_sync(0xffffffffu, mx1, 2));
        const float c0 = __expf(m0 - mx0);
        const float c1 = __expf(m1 - mx1);
        m0 = mx0; m1 = mx1;
        float ls0 = 0.f, ls1 = 0.f;
        #pragma unroll
        for (int nb = 0; nb < 8; nb++) {
            s[nb].x = __expf(s[nb].x - m0);
            s[nb].y = __expf(s[nb].y - m0);
            s[nb].z = __expf(s[nb].z - m1);
            s[nb].w = __expf(s[nb].w - m1);
            ls0 += s[nb].x + s[nb].y;
            ls1 += s[nb].z + s[nb].w;
        }
        l0 = l0 * c0 + ls0;
        l1 = l1 * c1 + ls1;
        #pragma unroll
        for (int i = 0; i < 16; i++) {
            o[i].x *= c0; o[i].y *= c0; o[i].z *= c1; o[i].w *= c1;
        }

        // O += P @ V (P A-frags via quad shuffles; P needs rna conversion)
        const int srcA = (lane & ~3) | (tig >> 1);
        const int srcB = srcA + 2;
        #pragma unroll
        for (int kb = 0; kb < 8; kb++) {
            float xA = __shfl_sync(0xffffffffu, s[kb].x, srcA);
            float yA = __shfl_sync(0xffffffffu, s[kb].y, srcA);
            float zA = __shfl_sync(0xffffffffu, s[kb].z, srcA);
            float wA = __shfl_sync(0xffffffffu, s[kb].w, srcA);
            float xB = __shfl_sync(0xffffffffu, s[kb].x, srcB);
            float yB = __shfl_sync(0xffffffffu, s[kb].y, srcB);
            float zB = __shfl_sync(0xffffffffu, s[kb].z, srcB);
            float wB = __shfl_sync(0xffffffffu, s[kb].w, srcB);
            uint32_t a[4];
            a[0] = f2tf32((tig & 1) ? yA : xA);
            a[1] = f2tf32((tig & 1) ? wA : zA);
            a[2] = f2tf32((tig & 1) ? yB : xB);
            a[3] = f2tf32((tig & 1) ? wB : zB);
            #pragma unroll
            for (int nb = 0; nb < 16; nb++) {
                uint32_t b[2];
                b[0] = __float_as_uint(Vs[(kb * 8 + tig    ) * VPAD + nb * 8 + gid]);
                b[1] = __float_as_uint(Vs[(kb * 8 + tig + 4) * VPAD + nb * 8 + gid]);
                mma_tf32(o[nb], a, b);
            }
        }
    }

    l0 += __shfl_xor_sync(0xffffffffu, l0, 1);
    l0 += __shfl_xor_sync(0xffffffffu, l0, 2);
    l1 += __shfl_xor_sync(0xffffffffu, l1, 1);
    l1 += __shfl_xor_sync(0xffffffffu, l1, 2);
    const float i0 = 1.f / l0, i1 = 1.f / l1;

    const int r0 = qt * AQ + wm + gid;
    float* O0 = g_o + ((size_t)h * S_TOT + r0) * HD;
    float* O1 = O0 + 8 * HD;
    #pragma unroll
    for (int nb = 0; nb < 16; nb++) {
        int col = nb * 8 + tig * 2;
        *(float2*)&O0[col] = make_float2(o[nb].x * i0, o[nb].y * i0);
        *(float2*)&O1[col] = make_float2(o[nb].z * i1, o[nb].w * i1);
    }
}

// ------- adapter 4-key cross-attention + merge (tf32-rounded hs) ----------------
// g_q is pre-scaled by SM_SCALE, so scores need no extra scale.
__global__ __launch_bounds__(128) void merge_adapter(const float* __restrict__ bscale)
{
    const int s = blockIdx.x, h = blockIdx.y, d = threadIdx.x;
    const int lane = d & 31, wid = d >> 5;
    __shared__ float wsum[4];
    __shared__ float sd[4];
    const size_t qidx = ((size_t)h * S_TOT + s) * HD + d;
    const float qv = g_q[qidx];
    const int hcol = h * HD + d;
    #pragma unroll
    for (int t = 0; t < ATOK; t++) {
        float p = qv * g_ka[t * DM + hcol];
        #pragma unroll
        for (int off = 16; off; off >>= 1) p += __shfl_xor_sync(0xffffffffu, p, off);
        if (lane == 0) wsum[wid] = p;
        __syncthreads();
        if (d == 0) sd[t] = wsum[0] + wsum[1] + wsum[2] + wsum[3];
        __syncthreads();
    }
    float d0 = sd[0], d1 = sd[1], d2 = sd[2], d3 = sd[3];
    float mx = fmaxf(fmaxf(d0, d1), fmaxf(d2, d3));
    float e0 = __expf(d0 - mx), e1 = __expf(d1 - mx);
    float e2 = __expf(d2 - mx), e3 = __expf(d3 - mx);
    float inv = 1.f / (e0 + e1 + e2 + e3);
    float vd = (e0 * g_va[0 * DM + hcol] + e1 * g_va[1 * DM + hcol] +
                e2 * g_va[2 * DM + hcol] + e3 * g_va[3 * DM + hcol]) * inv;
    g_hs[(size_t)s * DM + hcol] = tf32r(g_o[qidx] + bscale[0] * vd);
}

// -------------------------------- launch ---------------------------------------
extern "C" void kernel_launch(void* const* d_in, const int* in_sizes, int n_in,
                              void* d_out, int out_size)
{
    const float* hidden = (const float*)d_in[0];
    const float* enc    = (const float*)d_in[1];
    const float* adapt  = (const float*)d_in[2];
    const float* fcos   = (const float*)d_in[3];
    const float* fsin   = (const float*)d_in[4];
    const float* Wq  = (const float*)d_in[5];  const float* bq  = (const float*)d_in[6];
    const float* Wk  = (const float*)d_in[7];  const float* bk  = (const float*)d_in[8];
    const float* Wv  = (const float*)d_in[9];  const float* bv  = (const float*)d_in[10];
    const float* nqw = (const float*)d_in[11]; const float* nkw = (const float*)d_in[12];
    const float* Wqa = (const float*)d_in[13]; const float* bqa = (const float*)d_in[14];
    const float* Wka = (const float*)d_in[15]; const float* bka = (const float*)d_in[16];
    const float* Wva = (const float*)d_in[17]; const float* bva = (const float*)d_in[18];
    const float* naqw = (const float*)d_in[19]; const float* nakw = (const float*)d_in[20];
    const float* Wo  = (const float*)d_in[21]; const float* bo  = (const float*)d_in[22];
    const float* Woa = (const float*)d_in[23]; const float* boa = (const float*)d_in[24];
    const float* Wkad = (const float*)d_in[25]; const float* Wvad = (const float*)d_in[26];
    const float* bscale = (const float*)d_in[27];
    float* out = (float*)d_out;

    float *pq_img, *pk_img, *pv_img, *pq_txt, *pk_txt, *pv_txt, *ka, *va, *hs;
    float *chid, *cenc, *cad, *cWq, *cWk, *cWv, *cWqa, *cWka, *cWva, *cWo, *cWoa,
          *cWkad, *cWvad;
    cudaGetSymbolAddress((void**)&pq_img, g_pq_img);
    cudaGetSymbolAddress((void**)&pk_img, g_pk_img);
    cudaGetSymbolAddress((void**)&pv_img, g_pv_img);
    cudaGetSymbolAddress((void**)&pq_txt, g_pq_txt);
    cudaGetSymbolAddress((void**)&pk_txt, g_pk_txt);
    cudaGetSymbolAddress((void**)&pv_txt, g_pv_txt);
    cudaGetSymbolAddress((void**)&ka, g_ka);
    cudaGetSymbolAddress((void**)&va, g_va);
    cudaGetSymbolAddress((void**)&hs, g_hs);
    cudaGetSymbolAddress((void**)&chid, g_chid);
    cudaGetSymbolAddress((void**)&cenc, g_cenc);
    cudaGetSymbolAddress((void**)&cad, g_cad);
    cudaGetSymbolAddress((void**)&cWq, g_cWq);
    cudaGetSymbolAddress((void**)&cWk, g_cWk);
    cudaGetSymbolAddress((void**)&cWv, g_cWv);
    cudaGetSymbolAddress((void**)&cWqa, g_cWqa);
    cudaGetSymbolAddress((void**)&cWka, g_cWka);
    cudaGetSymbolAddress((void**)&cWva, g_cWva);
    cudaGetSymbolAddress((void**)&cWo, g_cWo);
    cudaGetSymbolAddress((void**)&cWoa, g_cWoa);
    cudaGetSymbolAddress((void**)&cWkad, g_cWkad);
    cudaGetSymbolAddress((void**)&cWvad, g_cWvad);

    cudaFuncSetAttribute(attn_mma, cudaFuncAttributeMaxDynamicSharedMemorySize,
                         ATTN_SMEM);
    cudaFuncSetAttribute(gemm_ca, cudaFuncAttributeMaxDynamicSharedMemorySize,
                         GSMEM);

    // --- pre-round everything the GEMMs consume ---
    CV13 cv;
    cv.e[0]  = { hidden, chid,  S_IMG * DM };
    cv.e[1]  = { enc,    cenc,  S_TXT * DM };
    cv.e[2]  = { adapt,  cad,   ATOK * ADIM };
    cv.e[3]  = { Wq,     cWq,   DM * DM };
    cv.e[4]  = { Wk,     cWk,   DM * DM };
    cv.e[5]  = { Wv,     cWv,   DM * DM };
    cv.e[6]  = { Wqa,    cWqa,  DM * DM };
    cv.e[7]  = { Wka,    cWka,  DM * DM };
    cv.e[8]  = { Wva,    cWva,  DM * DM };
    cv.e[9]  = { Wo,     cWo,   DM * DM };
    cv.e[10] = { Woa,    cWoa,  DM * DM };
    cv.e[11] = { Wkad,   cWkad, ADIM * DM };
    cv.e[12] = { Wvad,   cWvad, ADIM * DM };
    prep_cvt<<<dim3((DM * DM + 1023) / 1024, 13), 256>>>(cv);

    // --- all 6 QKV projections in one launch ---
    GB6 qkv;
    qkv.e[0] = { chid, cWq,  bq,  pq_img, S_IMG, DM };
    qkv.e[1] = { chid, cWk,  bk,  pk_img, S_IMG, DM };
    qkv.e[2] = { chid, cWv,  bv,  pv_img, S_IMG, DM };
    qkv.e[3] = { cenc, cWqa, bqa, pq_txt, S_TXT, DM };
    qkv.e[4] = { cenc, cWka, bka, pk_txt, S_TXT, DM };
    qkv.e[5] = { cenc, cWva, bva, pv_txt, S_TXT, DM };
    gemm_ca<<<dim3(DM / BN, S_IMG / BM, 6), 256, GSMEM>>>(qkv);

    // --- adapter K/V (M=4, K=1024) ---
    GB6 ad;
    ad.e[0] = { cad, cWkad, (const float*)0, ka, ATOK, ADIM };
    ad.e[1] = { cad, cWvad, (const float*)0, va, ATOK, ADIM };
    ad.e[2] = ad.e[0]; ad.e[3] = ad.e[0]; ad.e[4] = ad.e[0]; ad.e[5] = ad.e[0];
    gemm_ca<<<dim3(DM / BN, 1, 2), 256, GSMEM>>>(ad);

    // RMSNorm + RoPE + head layout (tf32-rounded, q pre-scaled)
    qkv_transform<<<dim3(S_TOT, NH), 128>>>(nqw, nkw, naqw, nakw, fcos, fsin);
    // joint flash attention (tf32 tensor cores, cp.async double buffer)
    attn_mma<<<dim3(S_TOT / AQ, NH), 256, ATTN_SMEM>>>();
    // adapter attention + merge (writes tf32-rounded hs)
    merge_adapter<<<dim3(S_TOT, NH), 128>>>(bscale);

    // --- both output projections in one launch ---
    GB6 op;
    op.e[0] = { hs + (size_t)S_TXT * DM, cWo,  bo,  out,                      S_IMG, DM };
    op.e[1] = { hs,                      cWoa, boa, out + (size_t)S_IMG * DM, S_TXT, DM };
    op.e[2] = op.e[0]; op.e[3] = op.e[0]; op.e[4] = op.e[0]; op.e[5] = op.e[0];
    gemm_ca<<<dim3(DM / BN, S_IMG / BM, 2), 256, GSMEM>>>(op);
}